// round 7
// baseline (speedup 1.0000x reference)
#include <cuda_runtime.h>
#include <cuda_bf16.h>
#include <mma.h>

using namespace nvcuda;

#define B_ 2
#define L_ 2048
#define D_ 128
#define H_ 8
#define HD_ 32
#define HB_ 16
#define QSCALE 0.2550348f
#define SLD 68

__device__ float g_Z[HB_ * L_];
__device__ float g_S[HB_ * L_];
__device__ float g_vv[HB_ * L_];
__device__ __nv_bfloat16 g_Q[HB_ * L_ * HD_];
__device__ __nv_bfloat16 g_K[HB_ * L_ * HD_];

__global__ void init_kernel() {
    int t = blockIdx.x * 256 + threadIdx.x;
    if (t < HB_ * L_) {
        g_Z[t] = 0.f;
        g_S[t] = 0.f;
    }
}

__global__ void qk_kernel(const float* __restrict__ x, const float* __restrict__ pe,
                          const float* __restrict__ Wq, const float* __restrict__ bq,
                          const float* __restrict__ Wk, const float* __restrict__ bk) {
    __shared__ float xs[16][D_];
    int row0 = blockIdx.x * 16;
    for (int i = threadIdx.x; i < 16 * D_; i += 256) {
        int r = i >> 7;
        int d = i & (D_ - 1);
        int row = row0 + r;
        int l = row & (L_ - 1);
        xs[r][d] = x[row * D_ + d] + pe[l * D_ + d];
    }
    __syncthreads();

    int c = threadIdx.x;
    float accq[16];
    float acck[16];
#pragma unroll
    for (int r = 0; r < 16; r++) {
        accq[r] = 0.f;
        acck[r] = 0.f;
    }
#pragma unroll 4
    for (int d = 0; d < D_; d++) {
        float wq = Wq[d * 256 + c];
        float wk = Wk[d * 256 + c];
#pragma unroll
        for (int r = 0; r < 16; r++) {
            float xv = xs[r][d];
            accq[r] = fmaf(xv, wq, accq[r]);
            acck[r] = fmaf(xv, wk, acck[r]);
        }
    }
    float bqv = bq[c];
    float bkv = bk[c];
    int h = c >> 5;
    int hd = c & 31;
#pragma unroll
    for (int r = 0; r < 16; r++) {
        int row = row0 + r;
        int b = row >> 11;
        int l = row & (L_ - 1);
        size_t off = ((size_t)(h * B_ + b) * L_ + l) * HD_ + hd;
        g_Q[off] = __float2bfloat16((accq[r] + bqv) * QSCALE);
        g_K[off] = __float2bfloat16(acck[r] + bkv);
    }
}

__global__ void v_kernel(const float* __restrict__ x, const float* __restrict__ Wv) {
    int t = blockIdx.x * 256 + threadIdx.x;
    int h = t & 7;
    int row = t >> 3;
    const float* xr = x + (size_t)row * D_;
    float acc = 0.f;
#pragma unroll 8
    for (int d = 0; d < D_; d++) acc = fmaf(xr[d], Wv[d * H_ + h], acc);
    float s = 1.f / (1.f + __expf(-acc));
    int b = row >> 11;
    int l = row & (L_ - 1);
    g_vv[(h * B_ + b) * L_ + (L_ - 1 - l)] = s;
}

// Pass 1: Z row sums. grid (32, 16, 4), block 128 (4 warps x 16 q rows).
// Each block: 64 q rows, k chunk of 512.
__global__ __launch_bounds__(128) void z_kernel() {
    __shared__ __nv_bfloat16 Qs[64 * HD_];
    __shared__ __nv_bfloat16 Ks[64 * HD_];
    __shared__ float Ss[4][16 * SLD];

    int hb = blockIdx.y;
    int q0 = blockIdx.x * 64;
    int kc0 = blockIdx.z * 512;
    int tid = threadIdx.x;
    int w = tid >> 5;
    int lane = tid & 31;

    const uint4* qsrc = (const uint4*)(g_Q + ((size_t)hb * L_ + q0) * HD_);
    uint4* qdst = (uint4*)Qs;
    for (int i = tid; i < 256; i += 128) qdst[i] = qsrc[i];
    __syncthreads();

    wmma::fragment<wmma::matrix_a, 16, 16, 16, __nv_bfloat16, wmma::row_major> a0, a1;
    wmma::load_matrix_sync(a0, Qs + w * 16 * HD_, HD_);
    wmma::load_matrix_sync(a1, Qs + w * 16 * HD_ + 16, HD_);

    float zacc = 0.f;
    int r = lane >> 1;
    int c0 = (lane & 1) * 32;

    for (int kt = 0; kt < 8; kt++) {
        __syncthreads();
        const uint4* ksrc = (const uint4*)(g_K + ((size_t)hb * L_ + kc0 + kt * 64) * HD_);
        uint4* kdst = (uint4*)Ks;
        for (int i = tid; i < 256; i += 128) kdst[i] = ksrc[i];
        __syncthreads();

#pragma unroll
        for (int n = 0; n < 4; n++) {
            wmma::fragment<wmma::matrix_b, 16, 16, 16, __nv_bfloat16, wmma::col_major> b0, b1;
            wmma::load_matrix_sync(b0, Ks + n * 16 * HD_, HD_);
            wmma::load_matrix_sync(b1, Ks + n * 16 * HD_ + 16, HD_);
            wmma::fragment<wmma::accumulator, 16, 16, 16, float> cf;
            wmma::fill_fragment(cf, 0.f);
            wmma::mma_sync(cf, a0, b0, cf);
            wmma::mma_sync(cf, a1, b1, cf);
            wmma::store_matrix_sync(&Ss[w][n * 16], cf, SLD, wmma::mem_row_major);
        }
        __syncwarp();

        const float* srow = &Ss[w][r * SLD + c0];
#pragma unroll
        for (int j = 0; j < 32; j++) zacc += exp2f(srow[j]);
    }

    zacc += __shfl_xor_sync(0xffffffffu, zacc, 1);
    if ((lane & 1) == 0) {
        atomicAdd(&g_Z[hb * L_ + q0 + w * 16 + r], zacc);
    }
}

// Pass 2: diagonal sums. grid (32, 16, 4), block 128.
// Each block: 64 q rows, k chunk of 512, per-warp 528-wide m window.
__global__ __launch_bounds__(128) void s_kernel() {
    __shared__ __nv_bfloat16 Qs[64 * HD_];
    __shared__ __nv_bfloat16 Ks[64 * HD_];
    __shared__ float invZs[64];
    __shared__ float vvs[512];
    __shared__ float Ss[4][16 * SLD];
    __shared__ float Sw[4][528];

    int hb = blockIdx.y;
    int q0 = blockIdx.x * 64;
    int kc0 = blockIdx.z * 512;
    if (kc0 + 511 < q0) return;

    int tid = threadIdx.x;
    int w = tid >> 5;
    int lane = tid & 31;

    const uint4* qsrc = (const uint4*)(g_Q + ((size_t)hb * L_ + q0) * HD_);
    uint4* qdst = (uint4*)Qs;
    for (int i = tid; i < 256; i += 128) qdst[i] = qsrc[i];
    if (tid < 64) invZs[tid] = 1.f / g_Z[hb * L_ + q0 + tid];
    for (int i = tid; i < 512; i += 128) vvs[i] = g_vv[hb * L_ + kc0 + i];
    for (int i = tid; i < 4 * 528; i += 128) (&Sw[0][0])[i] = 0.f;
    __syncthreads();

    wmma::fragment<wmma::matrix_a, 16, 16, 16, __nv_bfloat16, wmma::row_major> a0, a1;
    wmma::load_matrix_sync(a0, Qs + w * 16 * HD_, HD_);
    wmma::load_matrix_sync(a1, Qs + w * 16 * HD_ + 16, HD_);

    int q0w = q0 + w * 16;

    for (int kt = 0; kt < 8; kt++) {
        int k0 = kc0 + kt * 64;
        if (k0 + 63 < q0) continue;
        __syncthreads();
        const uint4* ksrc = (const uint4*)(g_K + ((size_t)hb * L_ + k0) * HD_);
        uint4* kdst = (uint4*)Ks;
        for (int i = tid; i < 256; i += 128) kdst[i] = ksrc[i];
        __syncthreads();

#pragma unroll
        for (int n = 0; n < 4; n++) {
            wmma::fragment<wmma::matrix_b, 16, 16, 16, __nv_bfloat16, wmma::col_major> b0, b1;
            wmma::load_matrix_sync(b0, Ks + n * 16 * HD_, HD_);
            wmma::load_matrix_sync(b1, Ks + n * 16 * HD_ + 16, HD_);
            wmma::fragment<wmma::accumulator, 16, 16, 16, float> cf;
            wmma::fill_fragment(cf, 0.f);
            wmma::mma_sync(cf, a0, b0, cf);
            wmma::mma_sync(cf, a1, b1, cf);
            wmma::store_matrix_sync(&Ss[w][n * 16], cf, SLD, wmma::mem_row_major);
        }
        __syncwarp();

        int mbase = k0 - q0w;
        for (int t = lane; t < 79; t += 32) {
            int dd = t - 15;
            int m = mbase + dd;
            if (m >= 0) {
                int rlo = dd < 0 ? -dd : 0;
                int rhi = dd > 48 ? 63 - dd : 15;
                float sum = 0.f;
                for (int rr = rlo; rr <= rhi; rr++) {
                    float e = exp2f(Ss[w][rr * SLD + rr + dd]);
                    sum = fmaf(e * invZs[w * 16 + rr], vvs[kt * 64 + rr + dd], sum);
                }
                Sw[w][kt * 64 + t] += sum;
            }
        }
        __syncwarp();
    }
    __syncthreads();

    int base = kc0 - q0;
    int mlo = base - 63;
    if (mlo < 0) mlo = 0;
    int mhi = base + 511;
    if (mhi > L_ - 1) mhi = L_ - 1;
    for (int m = mlo + tid; m <= mhi; m += 128) {
        float acc = 0.f;
#pragma unroll
        for (int wp = 0; wp < 4; wp++) {
            int idx = m - base + 16 * wp + 15;
            if (idx >= 0 && idx < 528) acc += Sw[wp][idx];
        }
        atomicAdd(&g_S[hb * L_ + m], acc);
    }
}

__global__ void out_kernel(float* __restrict__ out) {
    int t = blockIdx.x * 256 + threadIdx.x;
    int h = t & 7;
    int m = (t >> 3) & (L_ - 1);
    int b = t >> 14;
    const float* S = g_S + (h * B_ + b) * L_;
    float num = S[m];
    float cnt = 3.f;
    if (m > 0) num += S[m - 1]; else cnt = 2.f;
    if (m < L_ - 1) num += S[m + 1]; else cnt = 2.f;
    out[t] = num / cnt;
}

extern "C" void kernel_launch(void* const* d_in, const int* in_sizes, int n_in,
                              void* d_out, int out_size) {
    const float* x = (const float*)d_in[0];
    const float* pe = (const float*)d_in[1];
    const float* Wq = (const float*)d_in[2];
    const float* bq = (const float*)d_in[3];
    const float* Wk = (const float*)d_in[4];
    const float* bk = (const float*)d_in[5];
    const float* Wv = (const float*)d_in[6];
    float* out = (float*)d_out;

    init_kernel<<<128, 256>>>();
    qk_kernel<<<256, 256>>>(x, pe, Wq, bq, Wk, bk);
    v_kernel<<<128, 256>>>(x, Wv);
    z_kernel<<<dim3(32, 16, 4), 128>>>();
    s_kernel<<<dim3(32, 16, 4), 128>>>();
    out_kernel<<<128, 256>>>(out);
}

// round 10
// speedup vs baseline: 1.7716x; 1.7716x over previous
#include <cuda_runtime.h>
#include <cuda_bf16.h>
#include <mma.h>

using namespace nvcuda;

#define B_ 2
#define L_ 2048
#define D_ 128
#define H_ 8
#define HD_ 32
#define HB_ 16
#define QSCALE 0.2550348f

__device__ float g_Z[HB_ * L_];
__device__ float g_S[HB_ * L_];
__device__ float g_vv[HB_ * L_];
__device__ __nv_bfloat16 g_Q[HB_ * L_ * HD_];
__device__ __nv_bfloat16 g_K[HB_ * L_ * HD_];

__global__ void qk_kernel(const float* __restrict__ x, const float* __restrict__ pe,
                          const float* __restrict__ Wq, const float* __restrict__ bq,
                          const float* __restrict__ Wk, const float* __restrict__ bk) {
    __shared__ float xs[16][D_];
    int row0 = blockIdx.x * 16;
    int tg = blockIdx.x * 256 + threadIdx.x;
    if (tg < HB_ * L_) {
        g_Z[tg] = 0.f;
        g_S[tg] = 0.f;
    }
    for (int i = threadIdx.x; i < 16 * D_; i += 256) {
        int r = i >> 7;
        int d = i & (D_ - 1);
        int row = row0 + r;
        int l = row & (L_ - 1);
        xs[r][d] = x[row * D_ + d] + pe[l * D_ + d];
    }
    __syncthreads();

    int c = threadIdx.x;
    float accq[16];
    float acck[16];
#pragma unroll
    for (int r = 0; r < 16; r++) {
        accq[r] = 0.f;
        acck[r] = 0.f;
    }
#pragma unroll 4
    for (int d = 0; d < D_; d++) {
        float wq = Wq[d * 256 + c];
        float wk = Wk[d * 256 + c];
#pragma unroll
        for (int r = 0; r < 16; r++) {
            float xv = xs[r][d];
            accq[r] = fmaf(xv, wq, accq[r]);
            acck[r] = fmaf(xv, wk, acck[r]);
        }
    }
    float bqv = bq[c];
    float bkv = bk[c];
    int h = c >> 5;
    int hd = c & 31;
#pragma unroll
    for (int r = 0; r < 16; r++) {
        int row = row0 + r;
        int b = row >> 11;
        int l = row & (L_ - 1);
        size_t off = ((size_t)(h * B_ + b) * L_ + l) * HD_ + hd;
        g_Q[off] = __float2bfloat16((accq[r] + bqv) * QSCALE);
        g_K[off] = __float2bfloat16(acck[r] + bkv);
    }
}

__global__ void v_kernel(const float* __restrict__ x, const float* __restrict__ Wv) {
    int t = blockIdx.x * 256 + threadIdx.x;
    int h = t & 7;
    int row = t >> 3;
    const float* xr = x + (size_t)row * D_;
    float acc = 0.f;
#pragma unroll 8
    for (int d = 0; d < D_; d++) acc = fmaf(xr[d], Wv[d * H_ + h], acc);
    float s = 1.f / (1.f + __expf(-acc));
    int b = row >> 11;
    int l = row & (L_ - 1);
    g_vv[(h * B_ + b) * L_ + (L_ - 1 - l)] = s;
}

// Pass 1: Z row sums, exp2 direct from accumulator registers.
// Layout discovered at runtime by a probe MMA (A = I, B[k][c] = k + 16c).
// grid (32, 16, 4), block 128.
__global__ __launch_bounds__(128) void z_kernel() {
    __shared__ __nv_bfloat16 Qs[64 * HD_];
    __shared__ __nv_bfloat16 Ks[64 * HD_];
    __shared__ __nv_bfloat16 Pa[4][256];
    __shared__ __nv_bfloat16 Pb[4][256];
    __shared__ float zrow[4][16];

    int hb = blockIdx.y;
    int q0 = blockIdx.x * 64;
    int kc0 = blockIdx.z * 512;
    int tid = threadIdx.x;
    int w = tid >> 5;
    int lane = tid & 31;

    // probe: decode this thread's accumulator (row, col) mapping
    int rowi[8];
    int coli[8];
    for (int i = lane; i < 256; i += 32) {
        int pr = i >> 4;
        int pk = i & 15;
        Pa[w][i] = __float2bfloat16(pr == pk ? 1.f : 0.f);
        Pb[w][i] = __float2bfloat16((float)i);
    }
    __syncwarp();
    {
        wmma::fragment<wmma::matrix_a, 16, 16, 16, __nv_bfloat16, wmma::row_major> ap;
        wmma::fragment<wmma::matrix_b, 16, 16, 16, __nv_bfloat16, wmma::col_major> bp;
        wmma::fragment<wmma::accumulator, 16, 16, 16, float> cp;
        wmma::load_matrix_sync(ap, &Pa[w][0], 16);
        wmma::load_matrix_sync(bp, &Pb[w][0], 16);
        wmma::fill_fragment(cp, 0.f);
        wmma::mma_sync(cp, ap, bp, cp);
#pragma unroll
        for (int i = 0; i < 8; i++) {
            int v = (int)(cp.x[i] + 0.5f);
            rowi[i] = v & 15;
            coli[i] = v >> 4;
        }
    }

    const uint4* qsrc = (const uint4*)(g_Q + ((size_t)hb * L_ + q0) * HD_);
    uint4* qdst = (uint4*)Qs;
    for (int i = tid; i < 256; i += 128) qdst[i] = qsrc[i];
    __syncthreads();

    wmma::fragment<wmma::matrix_a, 16, 16, 16, __nv_bfloat16, wmma::row_major> a0, a1;
    wmma::load_matrix_sync(a0, Qs + w * 16 * HD_, HD_);
    wmma::load_matrix_sync(a1, Qs + w * 16 * HD_ + 16, HD_);

    float zpart[8];
#pragma unroll
    for (int i = 0; i < 8; i++) zpart[i] = 0.f;

    for (int kt = 0; kt < 8; kt++) {
        __syncthreads();
        const uint4* ksrc = (const uint4*)(g_K + ((size_t)hb * L_ + kc0 + kt * 64) * HD_);
        uint4* kdst = (uint4*)Ks;
        for (int i = tid; i < 256; i += 128) kdst[i] = ksrc[i];
        __syncthreads();

#pragma unroll
        for (int n = 0; n < 4; n++) {
            wmma::fragment<wmma::matrix_b, 16, 16, 16, __nv_bfloat16, wmma::col_major> b0, b1;
            wmma::load_matrix_sync(b0, Ks + n * 16 * HD_, HD_);
            wmma::load_matrix_sync(b1, Ks + n * 16 * HD_ + 16, HD_);
            wmma::fragment<wmma::accumulator, 16, 16, 16, float> cf;
            wmma::fill_fragment(cf, 0.f);
            wmma::mma_sync(cf, a0, b0, cf);
            wmma::mma_sync(cf, a1, b1, cf);
#pragma unroll
            for (int i = 0; i < 8; i++) zpart[i] += exp2f(cf.x[i]);
        }
    }

    if (lane < 16) zrow[w][lane] = 0.f;
    __syncwarp();
#pragma unroll
    for (int i = 0; i < 8; i++) atomicAdd(&zrow[w][rowi[i]], zpart[i]);
    __syncwarp();
    if (lane < 16) atomicAdd(&g_Z[hb * L_ + q0 + w * 16 + lane], zrow[w][lane]);
}

// Pass 2: diagonal sums. p computed in registers (probed layout), scattered
// to a skewed per-warp stash (column == diagonal id), conflict-free gather.
// grid (32, 16, 4), block 128.
__global__ __launch_bounds__(128) void s_kernel() {
    __shared__ __nv_bfloat16 Qs[64 * HD_];
    __shared__ __nv_bfloat16 Ks[64 * HD_];
    __shared__ __nv_bfloat16 Pa[4][256];
    __shared__ __nv_bfloat16 Pb[4][256];
    __shared__ float invZs[64];
    __shared__ float vvs[512];
    __shared__ float stash[4][16 * 80];
    __shared__ float Sw[4][528];

    int hb = blockIdx.y;
    int q0 = blockIdx.x * 64;
    int kc0 = blockIdx.z * 512;
    if (kc0 + 511 < q0) return;

    int tid = threadIdx.x;
    int w = tid >> 5;
    int lane = tid & 31;

    int rowi[8];
    int coli[8];
    for (int i = lane; i < 256; i += 32) {
        int pr = i >> 4;
        int pk = i & 15;
        Pa[w][i] = __float2bfloat16(pr == pk ? 1.f : 0.f);
        Pb[w][i] = __float2bfloat16((float)i);
    }
    __syncwarp();
    {
        wmma::fragment<wmma::matrix_a, 16, 16, 16, __nv_bfloat16, wmma::row_major> ap;
        wmma::fragment<wmma::matrix_b, 16, 16, 16, __nv_bfloat16, wmma::col_major> bp;
        wmma::fragment<wmma::accumulator, 16, 16, 16, float> cp;
        wmma::load_matrix_sync(ap, &Pa[w][0], 16);
        wmma::load_matrix_sync(bp, &Pb[w][0], 16);
        wmma::fill_fragment(cp, 0.f);
        wmma::mma_sync(cp, ap, bp, cp);
#pragma unroll
        for (int i = 0; i < 8; i++) {
            int v = (int)(cp.x[i] + 0.5f);
            rowi[i] = v & 15;
            coli[i] = v >> 4;
        }
    }

    const uint4* qsrc = (const uint4*)(g_Q + ((size_t)hb * L_ + q0) * HD_);
    uint4* qdst = (uint4*)Qs;
    for (int i = tid; i < 256; i += 128) qdst[i] = qsrc[i];
    if (tid < 64) invZs[tid] = 1.f / g_Z[hb * L_ + q0 + tid];
    for (int i = tid; i < 512; i += 128) vvs[i] = g_vv[hb * L_ + kc0 + i];
    for (int i = tid; i < 4 * 528; i += 128) (&Sw[0][0])[i] = 0.f;
    __syncthreads();

    wmma::fragment<wmma::matrix_a, 16, 16, 16, __nv_bfloat16, wmma::row_major> a0, a1;
    wmma::load_matrix_sync(a0, Qs + w * 16 * HD_, HD_);
    wmma::load_matrix_sync(a1, Qs + w * 16 * HD_ + 16, HD_);

    int q0w = q0 + w * 16;
    float iz[8];
    int soff[8];
#pragma unroll
    for (int i = 0; i < 8; i++) {
        iz[i] = invZs[w * 16 + rowi[i]];
        soff[i] = rowi[i] * 79 + 15;
    }
    float* stw = &stash[w][0];

    for (int kt = 0; kt < 8; kt++) {
        int k0 = kc0 + kt * 64;
        if (k0 + 63 < q0) continue;
        __syncthreads();
        const uint4* ksrc = (const uint4*)(g_K + ((size_t)hb * L_ + k0) * HD_);
        uint4* kdst = (uint4*)Ks;
        for (int i = tid; i < 256; i += 128) kdst[i] = ksrc[i];
        __syncthreads();

#pragma unroll
        for (int n = 0; n < 4; n++) {
            wmma::fragment<wmma::matrix_b, 16, 16, 16, __nv_bfloat16, wmma::col_major> b0, b1;
            wmma::load_matrix_sync(b0, Ks + n * 16 * HD_, HD_);
            wmma::load_matrix_sync(b1, Ks + n * 16 * HD_ + 16, HD_);
            wmma::fragment<wmma::accumulator, 16, 16, 16, float> cf;
            wmma::fill_fragment(cf, 0.f);
            wmma::mma_sync(cf, a0, b0, cf);
            wmma::mma_sync(cf, a1, b1, cf);
#pragma unroll
            for (int i = 0; i < 8; i++) {
                int c = n * 16 + coli[i];
                float p = exp2f(cf.x[i]) * iz[i] * vvs[kt * 64 + c];
                stw[soff[i] + c] = p;
            }
        }
        __syncwarp();

        int mbase = k0 - q0w;
        for (int t = lane; t < 79; t += 32) {
            int dd = t - 15;
            int m = mbase + dd;
            if (m >= 0) {
                int rlo = dd < 0 ? -dd : 0;
                int rhi = dd > 48 ? 63 - dd : 15;
                float sum = 0.f;
                for (int rr = rlo; rr <= rhi; rr++) {
                    sum += stw[rr * 80 + t];
                }
                Sw[w][kt * 64 + t] += sum;
            }
        }
        __syncwarp();
    }
    __syncthreads();

    int base = kc0 - q0;
    int mlo = base - 63;
    if (mlo < 0) mlo = 0;
    int mhi = base + 511;
    if (mhi > L_ - 1) mhi = L_ - 1;
    for (int m = mlo + tid; m <= mhi; m += 128) {
        float acc = 0.f;
#pragma unroll
        for (int wp = 0; wp < 4; wp++) {
            int idx = m - base + 16 * wp + 15;
            if (idx >= 0 && idx < 528) acc += Sw[wp][idx];
        }
        atomicAdd(&g_S[hb * L_ + m], acc);
    }
}

__global__ void out_kernel(float* __restrict__ out) {
    int t = blockIdx.x * 256 + threadIdx.x;
    int h = t & 7;
    int m = (t >> 3) & (L_ - 1);
    int b = t >> 14;
    const float* S = g_S + (h * B_ + b) * L_;
    float num = S[m];
    float cnt = 3.f;
    if (m > 0) num += S[m - 1]; else cnt = 2.f;
    if (m < L_ - 1) num += S[m + 1]; else cnt = 2.f;
    out[t] = num / cnt;
}

extern "C" void kernel_launch(void* const* d_in, const int* in_sizes, int n_in,
                              void* d_out, int out_size) {
    const float* x = (const float*)d_in[0];
    const float* pe = (const float*)d_in[1];
    const float* Wq = (const float*)d_in[2];
    const float* bq = (const float*)d_in[3];
    const float* Wk = (const float*)d_in[4];
    const float* bk = (const float*)d_in[5];
    const float* Wv = (const float*)d_in[6];
    float* out = (float*)d_out;

    qk_kernel<<<256, 256>>>(x, pe, Wq, bq, Wk, bk);
    v_kernel<<<128, 256>>>(x, Wv);
    z_kernel<<<dim3(32, 16, 4), 128>>>();
    s_kernel<<<dim3(32, 16, 4), 128>>>();
    out_kernel<<<128, 256>>>(out);
}